// round 4
// baseline (speedup 1.0000x reference)
#include <cuda_runtime.h>
#include <cstdint>

// Flash attention, fp32 SIMT, round 2:
//  - fma.rn.f32x2 packed FMAs (2 FLOP/instr) everywhere in both GEMMs
//  - natural row-major smem tiles, all fragment loads LDS.128/LDS.64
//  - QK^T pairs over k; P@V pairs over d with a pair-duplicated P buffer
//  - cp.async double-buffered K/V staging (overlap LDG with compute)

namespace {

constexpr int B  = 2;
constexpr int S  = 2048;
constexpr int H  = 16;
constexpr int DH = 128;

constexpr int BM = 64;
constexpr int BN = 64;
constexpr int NT = 256;

constexpr int TS = 132;                 // row stride (floats) for all tiles
constexpr int TILE_F = 64 * TS;         // 8448 floats per 64-row tile
// Qs | Ks[2] | Vs[2] | Psd  -> 6 tiles
constexpr int SMEM_BYTES = 6 * TILE_F * 4;   // 202,752 B

constexpr float SCALE = 0.08838834764831845f;  // 1/sqrt(128)

using ull = unsigned long long;

__device__ __forceinline__ ull fma2(ull a, ull b, ull c) {
    ull d;
    asm("fma.rn.f32x2 %0, %1, %2, %3;" : "=l"(d) : "l"(a), "l"(b), "l"(c));
    return d;
}
__device__ __forceinline__ ull mul2(ull a, ull b) {
    ull d;
    asm("mul.rn.f32x2 %0, %1, %2;" : "=l"(d) : "l"(a), "l"(b));
    return d;
}
__device__ __forceinline__ ull pack2(float x, float y) {
    ull r;
    asm("mov.b64 %0, {%1, %2};" : "=l"(r) : "f"(x), "f"(y));
    return r;
}
__device__ __forceinline__ void unpack2(ull v, float& lo, float& hi) {
    asm("mov.b64 {%0, %1}, %2;" : "=f"(lo), "=f"(hi) : "l"(v));
}
__device__ __forceinline__ void cpasync16(uint32_t saddr, const void* gaddr) {
    asm volatile("cp.async.cg.shared.global [%0], [%1], 16;\n"
                 :: "r"(saddr), "l"(gaddr));
}

__global__ __launch_bounds__(NT, 1)
void fa_fp32(const float* __restrict__ qg, const float* __restrict__ kg,
             const float* __restrict__ vg, float* __restrict__ out, int skv)
{
    extern __shared__ float sm[];
    float* Qs  = sm;                    // [64][TS]
    float* Ks  = sm + TILE_F;           // [2][64][TS]
    float* Vs  = sm + 3 * TILE_F;       // [2][64][TS]
    float* Psd = sm + 5 * TILE_F;       // [64][TS], entry pair (p,p) at [m][2n]

    const int tid = threadIdx.x;
    const int tx  = tid & 15;
    const int ty  = tid >> 4;
    const int qtile = blockIdx.x;
    const int b = blockIdx.y >> 4;      // H == 16
    const int h = blockIdx.y & 15;

    const size_t rs = (size_t)H * DH;   // 2048 floats
    const float* qp = qg + ((size_t)b * S + (size_t)qtile * BM) * rs + (size_t)h * DH;
    const float* kp = kg + (size_t)b * skv * rs + (size_t)h * DH;
    const float* vp = vg + (size_t)b * skv * rs + (size_t)h * DH;

    const uint32_t sKb = (uint32_t)__cvta_generic_to_shared(Ks);
    const uint32_t sVb = (uint32_t)__cvta_generic_to_shared(Vs);

    // ---- load Q tile once (natural layout, float4 copy) ----
    #pragma unroll
    for (int t = 0; t < (BM * DH / 4) / NT; t++) {   // 8 iters
        int idx = tid + t * NT;
        int row = idx >> 5;
        int d4  = (idx & 31) * 4;
        float4 f = *reinterpret_cast<const float4*>(qp + (size_t)row * rs + d4);
        *reinterpret_cast<float4*>(Qs + row * TS + d4) = f;
    }

    // ---- prefetch tile 0 into buffer 0 via cp.async ----
    {
        const float* kt = kp;
        const float* vt = vp;
        #pragma unroll
        for (int t = 0; t < 8; t++) {
            int idx = tid + t * NT;
            int row = idx >> 5;
            int d4  = (idx & 31) * 4;
            uint32_t so = (uint32_t)((row * TS + d4) * 4);
            cpasync16(sKb + so, kt + (size_t)row * rs + d4);
            cpasync16(sVb + so, vt + (size_t)row * rs + d4);
        }
        asm volatile("cp.async.commit_group;\n" ::: "memory");
    }

    // per-thread softmax state: rows m_i = ty + 16*i
    float m_run[4], l_run[4];
    ull oacc2[4][4];                    // (m_i, d pair c): d = 8*tx + 2c, 2c+1
    #pragma unroll
    for (int i = 0; i < 4; i++) {
        m_run[i] = -3.0e38f;
        l_run[i] = 0.0f;
        #pragma unroll
        for (int c = 0; c < 4; c++) oacc2[i][c] = 0ull;
    }

    const int ntiles = skv / BN;
    for (int tile = 0; tile < ntiles; tile++) {
        const int cur = tile & 1;
        float* Kb = Ks + cur * TILE_F;
        float* Vb = Vs + cur * TILE_F;

        // prefetch next tile into the other buffer, then wait for current
        if (tile + 1 < ntiles) {
            const float* kt = kp + (size_t)(tile + 1) * BN * rs;
            const float* vt = vp + (size_t)(tile + 1) * BN * rs;
            uint32_t bufo = (uint32_t)((cur ^ 1) * TILE_F * 4);
            #pragma unroll
            for (int t = 0; t < 8; t++) {
                int idx = tid + t * NT;
                int row = idx >> 5;
                int d4  = (idx & 31) * 4;
                uint32_t so = bufo + (uint32_t)((row * TS + d4) * 4);
                cpasync16(sKb + so, kt + (size_t)row * rs + d4);
                cpasync16(sVb + so, vt + (size_t)row * rs + d4);
            }
            asm volatile("cp.async.commit_group;\n" ::: "memory");
            asm volatile("cp.async.wait_group 1;\n" ::: "memory");
        } else {
            asm volatile("cp.async.wait_group 0;\n" ::: "memory");
        }
        __syncthreads();

        // ---- S = Q @ K^T : dot-product style, FFMA2 pairs over k ----
        ull acc2[4][4];
        #pragma unroll
        for (int i = 0; i < 4; i++)
            #pragma unroll
            for (int j = 0; j < 4; j++) acc2[i][j] = 0ull;

        #pragma unroll 2
        for (int kk = 0; kk < DH; kk += 4) {
            ulonglong2 qv[4], kv[4];
            #pragma unroll
            for (int i = 0; i < 4; i++)
                qv[i] = *reinterpret_cast<const ulonglong2*>(Qs + (ty + 16 * i) * TS + kk);
            #pragma unroll
            for (int j = 0; j < 4; j++)
                kv[j] = *reinterpret_cast<const ulonglong2*>(Kb + (tx + 16 * j) * TS + kk);
            #pragma unroll
            for (int i = 0; i < 4; i++)
                #pragma unroll
                for (int j = 0; j < 4; j++) {
                    acc2[i][j] = fma2(qv[i].x, kv[j].x, acc2[i][j]);
                    acc2[i][j] = fma2(qv[i].y, kv[j].y, acc2[i][j]);
                }
        }

        // ---- online softmax; write duplicated-pair P ----
        #pragma unroll
        for (int i = 0; i < 4; i++) {
            float a[4];
            float mx = -3.0e38f;
            #pragma unroll
            for (int j = 0; j < 4; j++) {
                float lo, hi;
                unpack2(acc2[i][j], lo, hi);
                a[j] = (lo + hi) * SCALE;
                mx = fmaxf(mx, a[j]);
            }
            #pragma unroll
            for (int o = 8; o >= 1; o >>= 1)
                mx = fmaxf(mx, __shfl_xor_sync(0xffffffffu, mx, o));

            float mnew  = fmaxf(m_run[i], mx);
            float alpha = __expf(m_run[i] - mnew);

            float ls = 0.0f;
            #pragma unroll
            for (int j = 0; j < 4; j++) {
                float p = __expf(a[j] - mnew);
                int n = tx + 16 * j;
                *reinterpret_cast<float2*>(Psd + (ty + 16 * i) * TS + 2 * n) =
                    make_float2(p, p);
                ls += p;
            }
            #pragma unroll
            for (int o = 8; o >= 1; o >>= 1)
                ls += __shfl_xor_sync(0xffffffffu, ls, o);

            l_run[i] = l_run[i] * alpha + ls;
            m_run[i] = mnew;

            ull a2 = pack2(alpha, alpha);
            #pragma unroll
            for (int c = 0; c < 4; c++) oacc2[i][c] = mul2(oacc2[i][c], a2);
        }
        __syncthreads();   // P visible to all

        // ---- O += P @ V : FFMA2 pairs over d, P pairs broadcast-duplicated ----
        #pragma unroll 2
        for (int n2 = 0; n2 < BN; n2 += 2) {
            ulonglong2 pf[4];   // ((p_n2,p_n2),(p_n2+1,p_n2+1)) for row m_i
            #pragma unroll
            for (int i = 0; i < 4; i++)
                pf[i] = *reinterpret_cast<const ulonglong2*>(
                            Psd + (ty + 16 * i) * TS + 2 * n2);
            #pragma unroll
            for (int u = 0; u < 2; u++) {
                const float* vrow = Vb + (n2 + u) * TS + 8 * tx;
                ulonglong2 v0 = *reinterpret_cast<const ulonglong2*>(vrow);
                ulonglong2 v1 = *reinterpret_cast<const ulonglong2*>(vrow + 4);
                #pragma unroll
                for (int i = 0; i < 4; i++) {
                    ull p = u ? pf[i].y : pf[i].x;
                    oacc2[i][0] = fma2(p, v0.x, oacc2[i][0]);
                    oacc2[i][1] = fma2(p, v0.y, oacc2[i][1]);
                    oacc2[i][2] = fma2(p, v1.x, oacc2[i][2]);
                    oacc2[i][3] = fma2(p, v1.y, oacc2[i][3]);
                }
            }
        }
        __syncthreads();   // PV reads done before next tile overwrites Psd/buffers
    }

    // ---- epilogue: normalize and store (d = 8*tx + 0..7) ----
    float* op = out + ((size_t)b * S + (size_t)qtile * BM) * rs + (size_t)h * DH;
    #pragma unroll
    for (int i = 0; i < 4; i++) {
        float inv = 1.0f / l_run[i];
        float o0, o1, o2, o3, o4, o5, o6, o7;
        unpack2(oacc2[i][0], o0, o1);
        unpack2(oacc2[i][1], o2, o3);
        unpack2(oacc2[i][2], o4, o5);
        unpack2(oacc2[i][3], o6, o7);
        float* dst = op + (size_t)(ty + 16 * i) * rs + 8 * tx;
        *reinterpret_cast<float4*>(dst)     = make_float4(o0 * inv, o1 * inv, o2 * inv, o3 * inv);
        *reinterpret_cast<float4*>(dst + 4) = make_float4(o4 * inv, o5 * inv, o6 * inv, o7 * inv);
    }
}

} // namespace

extern "C" void kernel_launch(void* const* d_in, const int* in_sizes, int n_in,
                              void* d_out, int out_size)
{
    const float* q = (const float*)d_in[0];
    const float* k = (const float*)d_in[1];
    const float* v = (const float*)d_in[2];
    float* out = (float*)d_out;

    const int skv = in_sizes[1] / (B * H * DH);

    cudaFuncSetAttribute(fa_fp32, cudaFuncAttributeMaxDynamicSharedMemorySize, SMEM_BYTES);

    dim3 grid(S / BM, B * H);
    fa_fp32<<<grid, NT, SMEM_BYTES>>>(q, k, v, out, skv);
}

// round 5
// speedup vs baseline: 1.0583x; 1.0583x over previous
#include <cuda_runtime.h>
#include <cstdint>

// Flash attention, fp32 SIMT, round 2:
//  - fma.rn.f32x2 packed FMAs (2 FLOP/instr) everywhere in both GEMMs
//  - natural row-major smem tiles, all fragment loads LDS.128/LDS.64
//  - QK^T pairs over k; P@V pairs over d with a pair-duplicated P buffer
//  - cp.async double-buffered K/V staging (overlap LDG with compute)

namespace {

constexpr int B  = 2;
constexpr int S  = 2048;
constexpr int H  = 16;
constexpr int DH = 128;

constexpr int BM = 64;
constexpr int BN = 64;
constexpr int NT = 256;

constexpr int TS = 132;                 // row stride (floats) for all tiles
constexpr int TILE_F = 64 * TS;         // 8448 floats per 64-row tile
// Qs | Ks[2] | Vs[2] | Psd  -> 6 tiles
constexpr int SMEM_BYTES = 6 * TILE_F * 4;   // 202,752 B

constexpr float SCALE = 0.08838834764831845f;  // 1/sqrt(128)

using ull = unsigned long long;

__device__ __forceinline__ ull fma2(ull a, ull b, ull c) {
    ull d;
    asm("fma.rn.f32x2 %0, %1, %2, %3;" : "=l"(d) : "l"(a), "l"(b), "l"(c));
    return d;
}
__device__ __forceinline__ ull mul2(ull a, ull b) {
    ull d;
    asm("mul.rn.f32x2 %0, %1, %2;" : "=l"(d) : "l"(a), "l"(b));
    return d;
}
__device__ __forceinline__ ull pack2(float x, float y) {
    ull r;
    asm("mov.b64 %0, {%1, %2};" : "=l"(r) : "f"(x), "f"(y));
    return r;
}
__device__ __forceinline__ void unpack2(ull v, float& lo, float& hi) {
    asm("mov.b64 {%0, %1}, %2;" : "=f"(lo), "=f"(hi) : "l"(v));
}
__device__ __forceinline__ void cpasync16(uint32_t saddr, const void* gaddr) {
    asm volatile("cp.async.cg.shared.global [%0], [%1], 16;\n"
                 :: "r"(saddr), "l"(gaddr));
}

__global__ __launch_bounds__(NT, 1)
void fa_fp32(const float* __restrict__ qg, const float* __restrict__ kg,
             const float* __restrict__ vg, float* __restrict__ out, int skv)
{
    extern __shared__ float sm[];
    float* Qs  = sm;                    // [64][TS]
    float* Ks  = sm + TILE_F;           // [2][64][TS]
    float* Vs  = sm + 3 * TILE_F;       // [2][64][TS]
    float* Psd = sm + 5 * TILE_F;       // [64][TS], entry pair (p,p) at [m][2n]

    const int tid = threadIdx.x;
    const int tx  = tid & 15;
    const int ty  = tid >> 4;
    const int qtile = blockIdx.x;
    const int b = blockIdx.y >> 4;      // H == 16
    const int h = blockIdx.y & 15;

    const size_t rs = (size_t)H * DH;   // 2048 floats
    const float* qp = qg + ((size_t)b * S + (size_t)qtile * BM) * rs + (size_t)h * DH;
    const float* kp = kg + (size_t)b * skv * rs + (size_t)h * DH;
    const float* vp = vg + (size_t)b * skv * rs + (size_t)h * DH;

    const uint32_t sKb = (uint32_t)__cvta_generic_to_shared(Ks);
    const uint32_t sVb = (uint32_t)__cvta_generic_to_shared(Vs);

    // ---- load Q tile once (natural layout, float4 copy) ----
    #pragma unroll
    for (int t = 0; t < (BM * DH / 4) / NT; t++) {   // 8 iters
        int idx = tid + t * NT;
        int row = idx >> 5;
        int d4  = (idx & 31) * 4;
        float4 f = *reinterpret_cast<const float4*>(qp + (size_t)row * rs + d4);
        *reinterpret_cast<float4*>(Qs + row * TS + d4) = f;
    }

    // ---- prefetch tile 0 into buffer 0 via cp.async ----
    {
        const float* kt = kp;
        const float* vt = vp;
        #pragma unroll
        for (int t = 0; t < 8; t++) {
            int idx = tid + t * NT;
            int row = idx >> 5;
            int d4  = (idx & 31) * 4;
            uint32_t so = (uint32_t)((row * TS + d4) * 4);
            cpasync16(sKb + so, kt + (size_t)row * rs + d4);
            cpasync16(sVb + so, vt + (size_t)row * rs + d4);
        }
        asm volatile("cp.async.commit_group;\n" ::: "memory");
    }

    // per-thread softmax state: rows m_i = ty + 16*i
    float m_run[4], l_run[4];
    ull oacc2[4][4];                    // (m_i, d pair c): d = 8*tx + 2c, 2c+1
    #pragma unroll
    for (int i = 0; i < 4; i++) {
        m_run[i] = -3.0e38f;
        l_run[i] = 0.0f;
        #pragma unroll
        for (int c = 0; c < 4; c++) oacc2[i][c] = 0ull;
    }

    const int ntiles = skv / BN;
    for (int tile = 0; tile < ntiles; tile++) {
        const int cur = tile & 1;
        float* Kb = Ks + cur * TILE_F;
        float* Vb = Vs + cur * TILE_F;

        // prefetch next tile into the other buffer, then wait for current
        if (tile + 1 < ntiles) {
            const float* kt = kp + (size_t)(tile + 1) * BN * rs;
            const float* vt = vp + (size_t)(tile + 1) * BN * rs;
            uint32_t bufo = (uint32_t)((cur ^ 1) * TILE_F * 4);
            #pragma unroll
            for (int t = 0; t < 8; t++) {
                int idx = tid + t * NT;
                int row = idx >> 5;
                int d4  = (idx & 31) * 4;
                uint32_t so = bufo + (uint32_t)((row * TS + d4) * 4);
                cpasync16(sKb + so, kt + (size_t)row * rs + d4);
                cpasync16(sVb + so, vt + (size_t)row * rs + d4);
            }
            asm volatile("cp.async.commit_group;\n" ::: "memory");
            asm volatile("cp.async.wait_group 1;\n" ::: "memory");
        } else {
            asm volatile("cp.async.wait_group 0;\n" ::: "memory");
        }
        __syncthreads();

        // ---- S = Q @ K^T : dot-product style, FFMA2 pairs over k ----
        ull acc2[4][4];
        #pragma unroll
        for (int i = 0; i < 4; i++)
            #pragma unroll
            for (int j = 0; j < 4; j++) acc2[i][j] = 0ull;

        #pragma unroll 2
        for (int kk = 0; kk < DH; kk += 4) {
            ulonglong2 qv[4], kv[4];
            #pragma unroll
            for (int i = 0; i < 4; i++)
                qv[i] = *reinterpret_cast<const ulonglong2*>(Qs + (ty + 16 * i) * TS + kk);
            #pragma unroll
            for (int j = 0; j < 4; j++)
                kv[j] = *reinterpret_cast<const ulonglong2*>(Kb + (tx + 16 * j) * TS + kk);
            #pragma unroll
            for (int i = 0; i < 4; i++)
                #pragma unroll
                for (int j = 0; j < 4; j++) {
                    acc2[i][j] = fma2(qv[i].x, kv[j].x, acc2[i][j]);
                    acc2[i][j] = fma2(qv[i].y, kv[j].y, acc2[i][j]);
                }
        }

        // ---- online softmax; write duplicated-pair P ----
        #pragma unroll
        for (int i = 0; i < 4; i++) {
            float a[4];
            float mx = -3.0e38f;
            #pragma unroll
            for (int j = 0; j < 4; j++) {
                float lo, hi;
                unpack2(acc2[i][j], lo, hi);
                a[j] = (lo + hi) * SCALE;
                mx = fmaxf(mx, a[j]);
            }
            #pragma unroll
            for (int o = 8; o >= 1; o >>= 1)
                mx = fmaxf(mx, __shfl_xor_sync(0xffffffffu, mx, o));

            float mnew  = fmaxf(m_run[i], mx);
            float alpha = __expf(m_run[i] - mnew);

            float ls = 0.0f;
            #pragma unroll
            for (int j = 0; j < 4; j++) {
                float p = __expf(a[j] - mnew);
                int n = tx + 16 * j;
                *reinterpret_cast<float2*>(Psd + (ty + 16 * i) * TS + 2 * n) =
                    make_float2(p, p);
                ls += p;
            }
            #pragma unroll
            for (int o = 8; o >= 1; o >>= 1)
                ls += __shfl_xor_sync(0xffffffffu, ls, o);

            l_run[i] = l_run[i] * alpha + ls;
            m_run[i] = mnew;

            ull a2 = pack2(alpha, alpha);
            #pragma unroll
            for (int c = 0; c < 4; c++) oacc2[i][c] = mul2(oacc2[i][c], a2);
        }
        __syncthreads();   // P visible to all

        // ---- O += P @ V : FFMA2 pairs over d, P pairs broadcast-duplicated ----
        #pragma unroll 2
        for (int n2 = 0; n2 < BN; n2 += 2) {
            ulonglong2 pf[4];   // ((p_n2,p_n2),(p_n2+1,p_n2+1)) for row m_i
            #pragma unroll
            for (int i = 0; i < 4; i++)
                pf[i] = *reinterpret_cast<const ulonglong2*>(
                            Psd + (ty + 16 * i) * TS + 2 * n2);
            #pragma unroll
            for (int u = 0; u < 2; u++) {
                const float* vrow = Vb + (n2 + u) * TS + 8 * tx;
                ulonglong2 v0 = *reinterpret_cast<const ulonglong2*>(vrow);
                ulonglong2 v1 = *reinterpret_cast<const ulonglong2*>(vrow + 4);
                #pragma unroll
                for (int i = 0; i < 4; i++) {
                    ull p = u ? pf[i].y : pf[i].x;
                    oacc2[i][0] = fma2(p, v0.x, oacc2[i][0]);
                    oacc2[i][1] = fma2(p, v0.y, oacc2[i][1]);
                    oacc2[i][2] = fma2(p, v1.x, oacc2[i][2]);
                    oacc2[i][3] = fma2(p, v1.y, oacc2[i][3]);
                }
            }
        }
        __syncthreads();   // PV reads done before next tile overwrites Psd/buffers
    }

    // ---- epilogue: normalize and store (d = 8*tx + 0..7) ----
    float* op = out + ((size_t)b * S + (size_t)qtile * BM) * rs + (size_t)h * DH;
    #pragma unroll
    for (int i = 0; i < 4; i++) {
        float inv = 1.0f / l_run[i];
        float o0, o1, o2, o3, o4, o5, o6, o7;
        unpack2(oacc2[i][0], o0, o1);
        unpack2(oacc2[i][1], o2, o3);
        unpack2(oacc2[i][2], o4, o5);
        unpack2(oacc2[i][3], o6, o7);
        float* dst = op + (size_t)(ty + 16 * i) * rs + 8 * tx;
        *reinterpret_cast<float4*>(dst)     = make_float4(o0 * inv, o1 * inv, o2 * inv, o3 * inv);
        *reinterpret_cast<float4*>(dst + 4) = make_float4(o4 * inv, o5 * inv, o6 * inv, o7 * inv);
    }
}

} // namespace

extern "C" void kernel_launch(void* const* d_in, const int* in_sizes, int n_in,
                              void* d_out, int out_size)
{
    const float* q = (const float*)d_in[0];
    const float* k = (const float*)d_in[1];
    const float* v = (const float*)d_in[2];
    float* out = (float*)d_out;

    const int skv = in_sizes[1] / (B * H * DH);

    cudaFuncSetAttribute(fa_fp32, cudaFuncAttributeMaxDynamicSharedMemorySize, SMEM_BYTES);

    dim3 grid(S / BM, B * H);
    fa_fp32<<<grid, NT, SMEM_BYTES>>>(q, k, v, out, skv);
}

// round 6
// speedup vs baseline: 4.2997x; 4.0629x over previous
#include <cuda_runtime.h>
#include <cuda_bf16.h>
#include <cstdint>

// Flash attention via mma.sync.m16n8k16.bf16 with 3-term hi/lo error
// compensation on QK^T and P·V (fp32-grade accuracy from bf16 tensor cores).
// Prep kernels split Q (pre-scaled), K, V into head-major bf16 hi/lo scratch.

namespace {

constexpr int B   = 2;
constexpr int S   = 2048;
constexpr int H   = 16;
constexpr int DH  = 128;
constexpr int SKV = 8192;

constexpr int BM = 64;
constexpr int BN = 64;
constexpr int NT = 128;

constexpr int KSTR   = 136;              // bf16 elems per smem row (pad: conflict-free ldmatrix)
constexpr int TILE_E = 64 * KSTR;        // 8704 elems per 64-row array
constexpr int SMEM_BYTES = 6 * TILE_E * 2;   // Qhi Qlo Khi Klo Vhi Vlo = 104448 B

constexpr float SCALE = 0.08838834764831845f;   // 1/sqrt(128), folded into Q at prep

// head-major bf16 hi/lo scratch: [b*H+h][s][d]
__device__ __nv_bfloat16 g_qhi[(size_t)B * H * S   * DH];
__device__ __nv_bfloat16 g_qlo[(size_t)B * H * S   * DH];
__device__ __nv_bfloat16 g_khi[(size_t)B * H * SKV * DH];
__device__ __nv_bfloat16 g_klo[(size_t)B * H * SKV * DH];
__device__ __nv_bfloat16 g_vhi[(size_t)B * H * SKV * DH];
__device__ __nv_bfloat16 g_vlo[(size_t)B * H * SKV * DH];

__device__ __forceinline__ void split4(float4 f, uint2& hi, uint2& lo)
{
    __nv_bfloat162 h0 = __float22bfloat162_rn(make_float2(f.x, f.y));
    __nv_bfloat162 h1 = __float22bfloat162_rn(make_float2(f.z, f.w));
    float2 r0 = __bfloat1622float2(h0);
    float2 r1 = __bfloat1622float2(h1);
    __nv_bfloat162 l0 = __float22bfloat162_rn(make_float2(f.x - r0.x, f.y - r0.y));
    __nv_bfloat162 l1 = __float22bfloat162_rn(make_float2(f.z - r1.x, f.w - r1.y));
    hi.x = reinterpret_cast<uint32_t&>(h0); hi.y = reinterpret_cast<uint32_t&>(h1);
    lo.x = reinterpret_cast<uint32_t&>(l0); lo.y = reinterpret_cast<uint32_t&>(l1);
}

// K/V: fp32 [b][s][h][d] -> head-major hi/lo
__global__ void prep_kv(const float* __restrict__ kg, const float* __restrict__ vg, int skv)
{
    size_t i = (size_t)blockIdx.x * blockDim.x + threadIdx.x;
    size_t total = (size_t)B * skv * H * (DH / 4);
    if (i >= total) return;
    int d = (int)(i % (DH / 4)) * 4;
    size_t t = i / (DH / 4);
    int h = (int)(t % H); t /= H;
    size_t s = t % skv;
    int b = (int)(t / skv);
    size_t src = (((size_t)b * skv + s) * H + h) * DH + d;
    size_t dst = (((size_t)(b * H + h) * skv) + s) * DH + d;
    uint2 hi, lo;
    split4(*reinterpret_cast<const float4*>(kg + src), hi, lo);
    *reinterpret_cast<uint2*>(g_khi + dst) = hi;
    *reinterpret_cast<uint2*>(g_klo + dst) = lo;
    split4(*reinterpret_cast<const float4*>(vg + src), hi, lo);
    *reinterpret_cast<uint2*>(g_vhi + dst) = hi;
    *reinterpret_cast<uint2*>(g_vlo + dst) = lo;
}

// Q: fp32 [b][s][h][d] -> head-major hi/lo, pre-scaled by 1/sqrt(D)
__global__ void prep_q(const float* __restrict__ qg)
{
    size_t i = (size_t)blockIdx.x * blockDim.x + threadIdx.x;
    size_t total = (size_t)B * S * H * (DH / 4);
    if (i >= total) return;
    int d = (int)(i % (DH / 4)) * 4;
    size_t t = i / (DH / 4);
    int h = (int)(t % H); t /= H;
    size_t s = t % S;
    int b = (int)(t / S);
    size_t src = (((size_t)b * S + s) * H + h) * DH + d;
    size_t dst = (((size_t)(b * H + h) * S) + s) * DH + d;
    float4 f = *reinterpret_cast<const float4*>(qg + src);
    f.x *= SCALE; f.y *= SCALE; f.z *= SCALE; f.w *= SCALE;
    uint2 hi, lo;
    split4(f, hi, lo);
    *reinterpret_cast<uint2*>(g_qhi + dst) = hi;
    *reinterpret_cast<uint2*>(g_qlo + dst) = lo;
}

__device__ __forceinline__ void mma16816(float* c, const uint32_t* a, const uint32_t* b)
{
    asm volatile(
        "mma.sync.aligned.m16n8k16.row.col.f32.bf16.bf16.f32 "
        "{%0,%1,%2,%3}, {%4,%5,%6,%7}, {%8,%9}, {%0,%1,%2,%3};"
        : "+f"(c[0]), "+f"(c[1]), "+f"(c[2]), "+f"(c[3])
        : "r"(a[0]), "r"(a[1]), "r"(a[2]), "r"(a[3]), "r"(b[0]), "r"(b[1]));
}
__device__ __forceinline__ void ldsm4(uint32_t* r, uint32_t addr)
{
    asm volatile("ldmatrix.sync.aligned.m8n8.x4.shared.b16 {%0,%1,%2,%3}, [%4];"
                 : "=r"(r[0]), "=r"(r[1]), "=r"(r[2]), "=r"(r[3]) : "r"(addr));
}
__device__ __forceinline__ void ldsm4t(uint32_t* r, uint32_t addr)
{
    asm volatile("ldmatrix.sync.aligned.m8n8.x4.trans.shared.b16 {%0,%1,%2,%3}, [%4];"
                 : "=r"(r[0]), "=r"(r[1]), "=r"(r[2]), "=r"(r[3]) : "r"(addr));
}
__device__ __forceinline__ void cp16(uint32_t saddr, const void* g)
{
    asm volatile("cp.async.cg.shared.global [%0], [%1], 16;" :: "r"(saddr), "l"(g));
}
__device__ __forceinline__ uint32_t pack_bf16x2(float x, float y)
{
    __nv_bfloat162 v = __float22bfloat162_rn(make_float2(x, y));
    return reinterpret_cast<uint32_t&>(v);
}

__global__ __launch_bounds__(NT)
void fa_mma(float* __restrict__ out, int skv)
{
    extern __shared__ __nv_bfloat16 sm[];
    const uint32_t sb  = (uint32_t)__cvta_generic_to_shared(sm);
    const uint32_t sQh = sb;
    const uint32_t sQl = sb + 1 * TILE_E * 2;
    const uint32_t sKh = sb + 2 * TILE_E * 2;
    const uint32_t sKl = sb + 3 * TILE_E * 2;
    const uint32_t sVh = sb + 4 * TILE_E * 2;
    const uint32_t sVl = sb + 5 * TILE_E * 2;

    const int tid  = threadIdx.x;
    const int warp = tid >> 5;
    const int lane = tid & 31;
    const int qtile = blockIdx.x;
    const int bh    = blockIdx.y;

    const size_t qoff = ((size_t)bh * S + (size_t)qtile * BM) * DH;
    const size_t koff = (size_t)bh * skv * DH;

    // ---- stage Q hi/lo (once) ----
    #pragma unroll
    for (int t = 0; t < 8; t++) {
        int idx = tid + t * NT;                    // 1024 chunks of 16B
        int row = idx >> 4;
        int c8  = (idx & 15) * 8;
        uint32_t so = (uint32_t)((row * KSTR + c8) * 2);
        cp16(sQh + so, g_qhi + qoff + (size_t)row * DH + c8);
        cp16(sQl + so, g_qlo + qoff + (size_t)row * DH + c8);
    }
    asm volatile("cp.async.commit_group;" ::: "memory");

    // ldmatrix lane-address patterns (elems)
    const int rowA = lane & 15;                    // A / V-trans pattern
    const int colA = (lane >> 4) << 3;
    const int rowB = (lane & 7) + (((lane >> 4) & 1) << 3);   // K B-frag pattern
    const int colB = ((lane >> 3) & 1) << 3;

    const uint32_t qhA = sQh + (uint32_t)(((warp * 16 + rowA) * KSTR + colA) * 2);
    const uint32_t qlA = sQl + (uint32_t)(((warp * 16 + rowA) * KSTR + colA) * 2);
    const uint32_t khB = sKh + (uint32_t)((rowB * KSTR + colB) * 2);
    const uint32_t klB = sKl + (uint32_t)((rowB * KSTR + colB) * 2);
    const uint32_t vhB = sVh + (uint32_t)((rowA * KSTR + colA) * 2);
    const uint32_t vlB = sVl + (uint32_t)((rowA * KSTR + colA) * 2);

    float Oacc[16][4];
    #pragma unroll
    for (int i = 0; i < 16; i++)
        #pragma unroll
        for (int j = 0; j < 4; j++) Oacc[i][j] = 0.0f;
    float m0 = -3.0e38f, m1 = -3.0e38f, l0 = 0.0f, l1 = 0.0f;

    const int ntiles = skv / BN;
    for (int tile = 0; tile < ntiles; tile++) {

        // ---- stage K/V hi/lo tile ----
        const size_t tb = koff + (size_t)tile * BN * DH;
        #pragma unroll
        for (int t = 0; t < 8; t++) {
            int idx = tid + t * NT;
            int row = idx >> 4;
            int c8  = (idx & 15) * 8;
            uint32_t so = (uint32_t)((row * KSTR + c8) * 2);
            const size_t go = tb + (size_t)row * DH + c8;
            cp16(sKh + so, g_khi + go);
            cp16(sKl + so, g_klo + go);
            cp16(sVh + so, g_vhi + go);
            cp16(sVl + so, g_vlo + go);
        }
        asm volatile("cp.async.commit_group;" ::: "memory");
        asm volatile("cp.async.wait_group 0;" ::: "memory");
        __syncthreads();

        // ---- S = Q K^T (3-term) : Sacc[8 n-blocks][4] ----
        float Sacc[8][4];
        #pragma unroll
        for (int i = 0; i < 8; i++)
            #pragma unroll
            for (int j = 0; j < 4; j++) Sacc[i][j] = 0.0f;

        #pragma unroll
        for (int kc = 0; kc < 8; kc++) {
            uint32_t ah[4], al[4];
            ldsm4(ah, qhA + kc * 32);
            ldsm4(al, qlA + kc * 32);
            #pragma unroll
            for (int nb2 = 0; nb2 < 4; nb2++) {
                uint32_t bhreg[4], blreg[4];
                ldsm4(bhreg, khB + nb2 * (16 * KSTR * 2) + kc * 32);
                ldsm4(blreg, klB + nb2 * (16 * KSTR * 2) + kc * 32);
                mma16816(Sacc[2 * nb2],     ah, bhreg);
                mma16816(Sacc[2 * nb2],     ah, blreg);
                mma16816(Sacc[2 * nb2],     al, bhreg);
                mma16816(Sacc[2 * nb2 + 1], ah, bhreg + 2);
                mma16816(Sacc[2 * nb2 + 1], ah, blreg + 2);
                mma16816(Sacc[2 * nb2 + 1], al, bhreg + 2);
            }
        }

        // ---- online softmax (Q was pre-scaled) ----
        float mx0 = -3.0e38f, mx1 = -3.0e38f;
        #pragma unroll
        for (int i = 0; i < 8; i++) {
            mx0 = fmaxf(mx0, fmaxf(Sacc[i][0], Sacc[i][1]));
            mx1 = fmaxf(mx1, fmaxf(Sacc[i][2], Sacc[i][3]));
        }
        mx0 = fmaxf(mx0, __shfl_xor_sync(0xffffffffu, mx0, 1));
        mx0 = fmaxf(mx0, __shfl_xor_sync(0xffffffffu, mx0, 2));
        mx1 = fmaxf(mx1, __shfl_xor_sync(0xffffffffu, mx1, 1));
        mx1 = fmaxf(mx1, __shfl_xor_sync(0xffffffffu, mx1, 2));

        const float mn0 = fmaxf(m0, mx0);
        const float mn1 = fmaxf(m1, mx1);
        const float a0  = __expf(m0 - mn0);
        const float a1  = __expf(m1 - mn1);

        float s0 = 0.0f, s1 = 0.0f;
        #pragma unroll
        for (int i = 0; i < 8; i++) {
            Sacc[i][0] = __expf(Sacc[i][0] - mn0);
            Sacc[i][1] = __expf(Sacc[i][1] - mn0);
            Sacc[i][2] = __expf(Sacc[i][2] - mn1);
            Sacc[i][3] = __expf(Sacc[i][3] - mn1);
            s0 += Sacc[i][0] + Sacc[i][1];
            s1 += Sacc[i][2] + Sacc[i][3];
        }
        s0 += __shfl_xor_sync(0xffffffffu, s0, 1);
        s0 += __shfl_xor_sync(0xffffffffu, s0, 2);
        s1 += __shfl_xor_sync(0xffffffffu, s1, 1);
        s1 += __shfl_xor_sync(0xffffffffu, s1, 2);

        l0 = l0 * a0 + s0;  m0 = mn0;
        l1 = l1 * a1 + s1;  m1 = mn1;

        #pragma unroll
        for (int i = 0; i < 16; i++) {
            Oacc[i][0] *= a0; Oacc[i][1] *= a0;
            Oacc[i][2] *= a1; Oacc[i][3] *= a1;
        }

        // ---- O += P V (3-term), P split in-registers ----
        #pragma unroll
        for (int kc = 0; kc < 4; kc++) {
            uint32_t ph[4], pl[4];
            const float* c0 = Sacc[2 * kc];
            const float* c1 = Sacc[2 * kc + 1];
            ph[0] = pack_bf16x2(c0[0], c0[1]);
            ph[1] = pack_bf16x2(c0[2], c0[3]);
            ph[2] = pack_bf16x2(c1[0], c1[1]);
            ph[3] = pack_bf16x2(c1[2], c1[3]);
            {
                __nv_bfloat162 h;
                float2 r;
                reinterpret_cast<uint32_t&>(h) = ph[0]; r = __bfloat1622float2(h);
                pl[0] = pack_bf16x2(c0[0] - r.x, c0[1] - r.y);
                reinterpret_cast<uint32_t&>(h) = ph[1]; r = __bfloat1622float2(h);
                pl[1] = pack_bf16x2(c0[2] - r.x, c0[3] - r.y);
                reinterpret_cast<uint32_t&>(h) = ph[2]; r = __bfloat1622float2(h);
                pl[2] = pack_bf16x2(c1[0] - r.x, c1[1] - r.y);
                reinterpret_cast<uint32_t&>(h) = ph[3]; r = __bfloat1622float2(h);
                pl[3] = pack_bf16x2(c1[2] - r.x, c1[3] - r.y);
            }
            #pragma unroll
            for (int db2 = 0; db2 < 8; db2++) {
                uint32_t vh[4], vl[4];
                ldsm4t(vh, vhB + kc * (16 * KSTR * 2) + db2 * 32);
                ldsm4t(vl, vlB + kc * (16 * KSTR * 2) + db2 * 32);
                mma16816(Oacc[2 * db2],     ph, vh);
                mma16816(Oacc[2 * db2],     ph, vl);
                mma16816(Oacc[2 * db2],     pl, vh);
                mma16816(Oacc[2 * db2 + 1], ph, vh + 2);
                mma16816(Oacc[2 * db2 + 1], ph, vl + 2);
                mma16816(Oacc[2 * db2 + 1], pl, vh + 2);
            }
        }
        __syncthreads();   // done reading smem before next tile's cp.async
    }

    // ---- epilogue: normalize, write out [b][s][h][d] ----
    const int b = bh >> 4, h = bh & 15;
    const float inv0 = 1.0f / l0;
    const float inv1 = 1.0f / l1;
    const int r0 = qtile * BM + warp * 16 + (lane >> 2);
    const size_t rs = (size_t)H * DH;
    float* o0 = out + ((size_t)b * S + r0)     * rs + (size_t)h * DH;
    float* o1 = out + ((size_t)b * S + r0 + 8) * rs + (size_t)h * DH;
    #pragma unroll
    for (int nb = 0; nb < 16; nb++) {
        int d = 8 * nb + 2 * (lane & 3);
        *reinterpret_cast<float2*>(o0 + d) = make_float2(Oacc[nb][0] * inv0, Oacc[nb][1] * inv0);
        *reinterpret_cast<float2*>(o1 + d) = make_float2(Oacc[nb][2] * inv1, Oacc[nb][3] * inv1);
    }
}

} // namespace

extern "C" void kernel_launch(void* const* d_in, const int* in_sizes, int n_in,
                              void* d_out, int out_size)
{
    const float* q = (const float*)d_in[0];
    const float* k = (const float*)d_in[1];
    const float* v = (const float*)d_in[2];
    float* out = (float*)d_out;

    const int skv = in_sizes[1] / (B * H * DH);

    {   // prep: split to bf16 hi/lo, head-major
        size_t nkv = (size_t)B * skv * H * (DH / 4);
        size_t nq  = (size_t)B * S   * H * (DH / 4);
        prep_kv<<<(unsigned)((nkv + 255) / 256), 256>>>(k, v, skv);
        prep_q <<<(unsigned)((nq  + 255) / 256), 256>>>(q);
    }

    cudaFuncSetAttribute(fa_mma, cudaFuncAttributeMaxDynamicSharedMemorySize, SMEM_BYTES);
    dim3 grid(S / BM, B * H);
    fa_mma<<<grid, NT, SMEM_BYTES>>>(out, skv);
}